// round 1
// baseline (speedup 1.0000x reference)
#include <cuda_runtime.h>
#include <math.h>

#define T    2048
#define F    1024
#define NB   64          // total batch
#define HB   32          // half batch
#define KSEL 20

// scratch (no allocs allowed)
__device__ float g_mags[NB * T];
__device__ int   g_idx[NB * KSEL];

// -------- kernel 1: per-(b,t) L2 norm over feature dim --------
// one warp per row; 8 float4 loads per lane, fully coalesced
__global__ void mag_kernel(const float* __restrict__ feat) {
    int warp = (blockIdx.x * blockDim.x + threadIdx.x) >> 5;  // 0 .. 64*2048-1
    int lane = threadIdx.x & 31;
    const float4* row = (const float4*)(feat + (size_t)warp * F);
    float s = 0.f;
#pragma unroll
    for (int i = 0; i < 8; i++) {
        float4 v = row[lane + i * 32];
        s += v.x * v.x + v.y * v.y + v.z * v.z + v.w * v.w;
    }
#pragma unroll
    for (int o = 16; o; o >>= 1) s += __shfl_xor_sync(0xffffffffu, s, o);
    if (lane == 0) g_mags[warp] = sqrtf(s);
}

// -------- kernel 2: top-K (stable, descending) + score mean --------
// blockIdx.x in [0,64): [0,32) = abnormal rows (batch 32+r, mask_abn),
//                       [32,64) = normal rows (batch r, mask_nor)
__global__ void topk_kernel(const float* __restrict__ scores,
                            const float* __restrict__ mask_abn,
                            const float* __restrict__ mask_nor,
                            float* __restrict__ out) {
    __shared__ float vals[T];
    __shared__ float rv[256];
    __shared__ int   ri[256];

    int b = blockIdx.x;
    int r, batch;
    const float* mask;
    if (b < HB) { r = b;      batch = HB + r; mask = mask_abn + (size_t)r * T; }
    else        { r = b - HB; batch = r;      mask = mask_nor + (size_t)r * T; }

    int tid = threadIdx.x;
    const float inv = 1.0f / 0.9f;   // 1/(1-P)
    for (int t = tid; t < T; t += blockDim.x) {
        float d = (mask[t] > 0.1f) ? inv : 0.0f;
        vals[t] = g_mags[batch * T + t] * d;
    }
    __syncthreads();

    for (int k = 0; k < KSEL; k++) {
        // local argmax, ascending scan + strict '>' keeps smallest index on tie
        float bv = -1.0f; int bi = T;
        for (int t = tid; t < T; t += blockDim.x) {
            float v = vals[t];
            if (v > bv) { bv = v; bi = t; }
        }
        rv[tid] = bv; ri[tid] = bi;
        __syncthreads();
        for (int s = blockDim.x >> 1; s > 0; s >>= 1) {
            if (tid < s) {
                float ov = rv[tid + s]; int oi = ri[tid + s];
                if (ov > rv[tid] || (ov == rv[tid] && oi < ri[tid])) {
                    rv[tid] = ov; ri[tid] = oi;
                }
            }
            __syncthreads();
        }
        if (tid == 0) {
            g_idx[b * KSEL + k] = ri[0];
            vals[ri[0]] = -1.0f;        // vals >= 0, so -1 never re-selected
        }
        __syncthreads();
    }

    // mean of selected scores
    if (tid < KSEL) {
        int idx = g_idx[b * KSEL + tid];
        rv[tid] = scores[(size_t)batch * T + idx];
    }
    __syncthreads();
    if (tid == 0) {
        float s = 0.f;
#pragma unroll
        for (int k = 0; k < KSEL; k++) s += rv[k];
        // b<32 -> score_abnormal[b] at out[b]; b>=32 -> score_normal at out[b]
        out[b] = s / (float)KSEL;
    }
}

// -------- kernel 3: gather selected feature rows --------
// 64*20 = 1280 blocks of 256 threads; each copies one 4KB row as float4s
__global__ void gather_kernel(const float* __restrict__ feat,
                              float* __restrict__ out) {
    int blk = blockIdx.x;
    int row = blk / KSEL;           // 0..63 (abn rows first, then nor)
    int k   = blk % KSEL;
    int batch = (row < HB) ? (HB + row) : (row - HB);
    int idx = g_idx[row * KSEL + k];
    const float4* src = (const float4*)(feat + ((size_t)batch * T + idx) * F);
    // layout: [64 scores][abn 32*20*1024][nor 32*20*1024] — rows 0..63 contiguous
    float4* dst = (float4*)(out + 64 + ((size_t)row * KSEL + k) * F);
    dst[threadIdx.x] = src[threadIdx.x];
}

extern "C" void kernel_launch(void* const* d_in, const int* in_sizes, int n_in,
                              void* d_out, int out_size) {
    const float* feat   = (const float*)d_in[0];
    const float* scores = (const float*)d_in[1];
    const float* mabn   = (const float*)d_in[2];
    const float* mnor   = (const float*)d_in[3];
    float* out = (float*)d_out;

    // 64*2048 rows, 1 warp each, 8 warps/block
    mag_kernel<<<(NB * T) / 8, 256>>>(feat);
    topk_kernel<<<NB, 256>>>(scores, mabn, mnor, out);
    gather_kernel<<<NB * KSEL, 256>>>(feat, out);
}

// round 2
// speedup vs baseline: 1.1917x; 1.1917x over previous
#include <cuda_runtime.h>
#include <math.h>

#define T    2048
#define F    1024
#define NB   64          // total batch
#define HB   32          // half batch
#define KSEL 20

// scratch (no allocs allowed)
__device__ float g_mags[NB * T];

// -------- kernel 1: per-(b,t) L2 norm over feature dim --------
// one warp per row; 8 float4 loads per lane, fully coalesced. HBM-bound.
__global__ void mag_kernel(const float* __restrict__ feat) {
    int warp = (blockIdx.x * blockDim.x + threadIdx.x) >> 5;  // 0 .. 64*2048-1
    int lane = threadIdx.x & 31;
    const float4* row = (const float4*)(feat + (size_t)warp * F);
    float s = 0.f;
#pragma unroll
    for (int i = 0; i < 8; i++) {
        float4 v = row[lane + i * 32];
        s += v.x * v.x + v.y * v.y + v.z * v.z + v.w * v.w;
    }
#pragma unroll
    for (int o = 16; o; o >>= 1) s += __shfl_xor_sync(0xffffffffu, s, o);
    if (lane == 0) g_mags[warp] = sqrtf(s);
}

// -------- kernel 2: fused top-K + score mean + feature gather --------
// 64 blocks of 256 threads. blockIdx.x in [0,32): abnormal (batch 32+r),
// [32,64): normal (batch r). Candidates live in registers (8/thread);
// each of the 20 selection rounds is: 8 reg compares -> warp shfl argmax
// -> 1-thread scan of 8 warp winners. Stable lowest-index tie-break
// matches jax.lax.top_k.
__global__ void topk_gather_kernel(const float* __restrict__ feat,
                                   const float* __restrict__ scores,
                                   const float* __restrict__ mask_abn,
                                   const float* __restrict__ mask_nor,
                                   float* __restrict__ out) {
    __shared__ float wrv[8];
    __shared__ int   wri[8];
    __shared__ int   s_win;
    __shared__ int   s_idx[KSEL];
    __shared__ float s_sc[KSEL];

    int b = blockIdx.x;
    int tid = threadIdx.x;
    int lane = tid & 31;
    int wid = tid >> 5;

    int batch;
    const float* mask;
    if (b < HB) { batch = HB + b; mask = mask_abn + (size_t)b * T; }
    else        { batch = b - HB; mask = mask_nor + (size_t)(b - HB) * T; }

    const float inv = 1.0f / 0.9f;   // 1/(1-P)
    float v[8];
#pragma unroll
    for (int j = 0; j < 8; j++) {
        int t = tid + j * 256;       // index = (j<<8) | tid
        float d = (mask[t] > 0.1f) ? inv : 0.0f;
        v[j] = g_mags[batch * T + t] * d;
    }

    for (int k = 0; k < KSEL; k++) {
        // local argmax over 8 registers (ascending j + strict '>' keeps
        // the smallest index since index grows with j)
        float bv = -1.0f; int bi = 1 << 30;
#pragma unroll
        for (int j = 0; j < 8; j++) {
            if (v[j] > bv) { bv = v[j]; bi = tid + j * 256; }
        }
        // warp argmax, smaller index wins ties
#pragma unroll
        for (int o = 16; o; o >>= 1) {
            float ov = __shfl_xor_sync(0xffffffffu, bv, o);
            int   oi = __shfl_xor_sync(0xffffffffu, bi, o);
            if (ov > bv || (ov == bv && oi < bi)) { bv = ov; bi = oi; }
        }
        if (lane == 0) { wrv[wid] = bv; wri[wid] = bi; }
        __syncthreads();
        if (tid == 0) {
            float fv = wrv[0]; int fi = wri[0];
#pragma unroll
            for (int w = 1; w < 8; w++) {
                float ov = wrv[w]; int oi = wri[w];
                if (ov > fv || (ov == fv && oi < fi)) { fv = ov; fi = oi; }
            }
            s_idx[k] = fi;
            s_win    = fi;
        }
        __syncthreads();
        int w = s_win;
        if ((w & 255) == tid) v[w >> 8] = -1.0f;   // remove winner (vals >= 0)
    }

    // mean of selected scores
    if (tid < KSEL) s_sc[tid] = scores[(size_t)batch * T + s_idx[tid]];
    __syncthreads();
    if (tid == 0) {
        float s = 0.f;
#pragma unroll
        for (int k = 0; k < KSEL; k++) s += s_sc[k];
        out[b] = s / (float)KSEL;    // [0,32)=score_abnormal, [32,64)=score_normal
    }

    // gather 20 selected feature rows: one float4 per thread per row,
    // 20 independent copies -> high MLP
    float* dst_base = out + 64 + (size_t)b * KSEL * F;
#pragma unroll
    for (int k = 0; k < KSEL; k++) {
        const float4* src =
            (const float4*)(feat + ((size_t)batch * T + s_idx[k]) * F);
        float4* dst = (float4*)(dst_base + (size_t)k * F);
        dst[tid] = src[tid];
    }
}

extern "C" void kernel_launch(void* const* d_in, const int* in_sizes, int n_in,
                              void* d_out, int out_size) {
    const float* feat   = (const float*)d_in[0];
    const float* scores = (const float*)d_in[1];
    const float* mabn   = (const float*)d_in[2];
    const float* mnor   = (const float*)d_in[3];
    float* out = (float*)d_out;

    mag_kernel<<<(NB * T) / 8, 256>>>(feat);
    topk_gather_kernel<<<NB, 256>>>(feat, scores, mabn, mnor, out);
}